// round 15
// baseline (speedup 1.0000x reference)
#include <cuda_runtime.h>
#include <cuda_fp16.h>
#include <math.h>
#include <stdint.h>

#define NN 100000
#define EE 300000
#define DD 256
#define FDIM 512
#define LL 5
#define GG 4000
#define NUM_BOND_C 2
#define BN_EPS 1e-5f
#define MPAD_N 100096   // 782*128
#define MPAD_G 4096     // 32*128
#define NB_SCAN 391     // ceil(NN/256)

// ---------------- scratch (device globals: no allocation allowed) ----------------
__device__ float g_h[(size_t)NN * DD];
__device__ float g_agg[(size_t)NN * DD];
__device__ float g_stat[2 * DD];            // zero-init; reset by GEMM2 last CTA
__device__ float g_ab[2 * DD];
__device__ float g_ssum[(size_t)GG * DD];   // zero-init; reset by pm_kernel
__device__ float g_cnt[GG];                 // zero-init; reset by pm_kernel
__device__ float g_pm[(size_t)GG * DD];
__device__ float g_gfeat[(size_t)GG * FDIM];
__device__ float g_hid[(size_t)GG * (FDIM / 2)];
__device__ uint4 g_a16b[(size_t)(MPAD_N / 16) * (FDIM / 16) * 64];
__device__ uint4 g_w16[393216];
__device__ int g_ctr;                        // zero-init; reset by last CTA
// CSR (by destination)
__device__ int g_deg[NN];
__device__ int g_fill[NN];
__device__ int g_rs[NN + 1];
__device__ int g_bsum[512];
__device__ int g_srcs[EE];
__device__ int g_attrs[EE];

__device__ __forceinline__ float softplus_f(float x) {
    return fmaxf(x, 0.0f) + log1pf(expf(-fabsf(x)));
}

__device__ __forceinline__ void red_add_f32(float* p, float v) {
    asm volatile("red.global.add.f32 [%0], %1;" :: "l"(p), "f"(v) : "memory");
}
__device__ __forceinline__ void red_add_v4(float* p, float x, float y, float z, float w) {
    asm volatile("red.global.add.v4.f32 [%0], {%1,%2,%3,%4};"
                 :: "l"(p), "f"(x), "f"(y), "f"(z), "f"(w) : "memory");
}

// ---------------- fp16 split helpers ----------------
__device__ __forceinline__ void packhl(float x, float y, uint32_t& hi, uint32_t& lo) {
    __half2 h = __floats2half2_rn(x, y);
    float2 hf = __half22float2(h);
    __half2 l = __floats2half2_rn(x - hf.x, y - hf.y);
    hi = *reinterpret_cast<uint32_t*>(&h);
    lo = *reinterpret_cast<uint32_t*>(&l);
}

__device__ __forceinline__ void mma16(float* c, const uint32_t* a, uint32_t b0, uint32_t b1) {
    asm volatile(
        "mma.sync.aligned.m16n8k16.row.col.f32.f16.f16.f32 "
        "{%0,%1,%2,%3},{%4,%5,%6,%7},{%8,%9},{%0,%1,%2,%3};"
        : "+f"(c[0]), "+f"(c[1]), "+f"(c[2]), "+f"(c[3])
        : "r"(a[0]), "r"(a[1]), "r"(a[2]), "r"(a[3]), "r"(b0), "r"(b1));
}

__device__ __forceinline__ void cpa16(void* dst, const void* src, int srcBytes) {
    uint32_t d = (uint32_t)__cvta_generic_to_shared(dst);
    asm volatile("cp.async.cg.shared.global [%0], [%1], 16, %2;"
                 :: "r"(d), "l"(src), "r"(srcBytes) : "memory");
}
__device__ __forceinline__ void cpa16f(void* dst, const void* src) {
    uint32_t d = (uint32_t)__cvta_generic_to_shared(dst);
    asm volatile("cp.async.cg.shared.global [%0], [%1], 16;" :: "r"(d), "l"(src) : "memory");
}
__device__ __forceinline__ void cp_commit() {
    asm volatile("cp.async.commit_group;" ::: "memory");
}
__device__ __forceinline__ void cp_wait0() {
    asm volatile("cp.async.wait_group 0;" ::: "memory");
}

// ---------------- CSR build ----------------
__global__ void csr_zero(int* deg, int* fill) {
    int i = blockIdx.x * blockDim.x + threadIdx.x;
    if (i < NN) { deg[i] = 0; fill[i] = 0; }
}
__global__ void csr_count(const int* __restrict__ edge_index, int* __restrict__ deg) {
    int e = blockIdx.x * blockDim.x + threadIdx.x;
    if (e < EE) atomicAdd(&deg[edge_index[EE + e]], 1);
}
__global__ void csr_scan1(const int* __restrict__ deg, int* __restrict__ rs,
                          int* __restrict__ bsum) {
    __shared__ int sm[256];
    int tid = threadIdx.x;
    int i = blockIdx.x * 256 + tid;
    int v = (i < NN) ? deg[i] : 0;
    sm[tid] = v;
    __syncthreads();
#pragma unroll
    for (int o = 1; o < 256; o <<= 1) {
        int t = (tid >= o) ? sm[tid - o] : 0;
        __syncthreads();
        if (tid >= o) sm[tid] += t;
        __syncthreads();
    }
    if (i < NN) rs[i] = sm[tid] - v;
    if (tid == 255) bsum[blockIdx.x] = sm[255];
}
__global__ void csr_scan2(int* __restrict__ bsum) {
    __shared__ int sm[512];
    int tid = threadIdx.x;
    int v = (tid < NB_SCAN) ? bsum[tid] : 0;
    sm[tid] = v;
    __syncthreads();
#pragma unroll
    for (int o = 1; o < 512; o <<= 1) {
        int t = (tid >= o) ? sm[tid - o] : 0;
        __syncthreads();
        if (tid >= o) sm[tid] += t;
        __syncthreads();
    }
    if (tid < NB_SCAN) bsum[tid] = sm[tid] - v;
}
__global__ void csr_scan3(int* __restrict__ rs, const int* __restrict__ bsum) {
    int i = blockIdx.x * 256 + threadIdx.x;
    if (i < NN) rs[i] += bsum[blockIdx.x];
    if (i == 0) rs[NN] = EE;
}
__global__ void csr_place(const int* __restrict__ edge_index,
                          const int* __restrict__ edge_attr,
                          const int* __restrict__ rs, int* __restrict__ fill,
                          int* __restrict__ srcs, int* __restrict__ attrs) {
    int e = blockIdx.x * blockDim.x + threadIdx.x;
    if (e >= EE) return;
    int d = edge_index[EE + e];
    int p = rs[d] + atomicAdd(&fill[d], 1);
    srcs[p] = edge_index[e];
    attrs[p] = edge_attr[e];
}

// ---------------- gather ----------------
__global__ void gather_edges_kernel(const float* __restrict__ h,
                                    const int* __restrict__ srcs,
                                    const int* __restrict__ attrs,
                                    const int* __restrict__ rs,
                                    const float* __restrict__ emb,
                                    float* __restrict__ agg) {
    int node = blockIdx.x * (blockDim.x >> 5) + (threadIdx.x >> 5);
    if (node >= NN) return;
    int lane = threadIdx.x & 31;
    int c0 = lane * 4, c1 = c0 + 128;
    const float* hn = h + (size_t)node * DD;
    const float* es = emb + (size_t)(NUM_BOND_C - 1) * DD;
    float4 v0 = *(const float4*)(hn + c0);
    float4 v1 = *(const float4*)(hn + c1);
    float4 e0 = *(const float4*)(es + c0);
    float4 e1 = *(const float4*)(es + c1);
    float4 a0 = make_float4(v0.x + e0.x, v0.y + e0.y, v0.z + e0.z, v0.w + e0.w);
    float4 a1 = make_float4(v1.x + e1.x, v1.y + e1.y, v1.z + e1.z, v1.w + e1.w);
    int p0 = rs[node], p1 = rs[node + 1];
    for (int p = p0; p < p1; p++) {
        int s = srcs[p], a = attrs[p];
        const float* hs = h + (size_t)s * DD;
        const float* eb = emb + (size_t)a * DD;
        float4 h0 = *(const float4*)(hs + c0);
        float4 h1 = *(const float4*)(hs + c1);
        float4 b0 = *(const float4*)(eb + c0);
        float4 b1 = *(const float4*)(eb + c1);
        a0.x += h0.x + b0.x; a0.y += h0.y + b0.y; a0.z += h0.z + b0.z; a0.w += h0.w + b0.w;
        a1.x += h1.x + b1.x; a1.y += h1.y + b1.y; a1.z += h1.z + b1.z; a1.w += h1.w + b1.w;
    }
    float* ag = agg + (size_t)node * DD;
    *(float4*)(ag + c0) = a0;
    *(float4*)(ag + c1) = a1;
}

// ---------------- B16 converter (batched over L weight slices) ----------------
__global__ void conv_b16(const float* __restrict__ W, uint4* __restrict__ dst, int K, int N,
                         int L) {
    int Q = K >> 4;
    int per = (N >> 3) * Q;
    int wid = blockIdx.x * (blockDim.x >> 5) + (threadIdx.x >> 5);
    if (wid >= per * L) return;
    int l = wid / per;
    int r = wid - l * per;
    const float* Wl = W + (size_t)l * K * N;
    uint4* dl = dst + (size_t)l * per * 32;
    int bn = r / Q, q = r - bn * Q;
    int lane = threadIdx.x & 31, g = lane >> 2, t = lane & 3;
    int n = bn * 8 + g;
    int k0 = q * 16 + 2 * t, k1 = k0 + 8;
    uint4 v;
    uint32_t l0, l1;
    packhl(Wl[(size_t)k0 * N + n], Wl[(size_t)(k0 + 1) * N + n], v.x, l0);
    packhl(Wl[(size_t)k1 * N + n], Wl[(size_t)(k1 + 1) * N + n], v.y, l1);
    v.z = l0;
    v.w = l1;
    dl[(size_t)r * 32 + lane] = v;
}

// ---------------- fp16x3 tensor-core GEMM (R12 config + last-block BN finalize) ----
#define GEMM_SMEM_BYTES 65536

__global__ __launch_bounds__(256, 2)
void gemm_f16(const uint4* __restrict__ A16, const float* __restrict__ Afp,
              const uint4* __restrict__ B16, const float* __restrict__ bias,
              float* __restrict__ C, uint4* __restrict__ O16, int M, int Qa, int Nc,
              int act, float* __restrict__ stat, int Qout,
              const float* __restrict__ gammap, const float* __restrict__ betap,
              float* __restrict__ abp, int* __restrict__ ctr) {
    extern __shared__ uint4 sm4[];
    __shared__ int s_last;
    const int tid = threadIdx.x, lane = tid & 31, w = tid >> 5;
    const int g = lane >> 2, t = lane & 3;
    const int wm = (w >> 1) * 32, wn = (w & 1) * 64;
    const int brow = blockIdx.y * 128, bcol = blockIdx.x * 128;
    const bool a32 = (Afp != nullptr);
    const int K = Qa << 4;

    const uint4* asrc[4];
    uint4* adst[4];
    const uint4* bsrc[4];
    uint4* bdst[4];
#pragma unroll
    for (int j = 0; j < 4; j++) {
        int u = tid + j * 256;
        {
            int chunk = u >> 6, wd = u & 63;
            int bm = chunk >> 1, ql = chunk & 1;
            asrc[j] = A16 + ((size_t)((brow >> 4) + bm) * Qa + ql) * 64 + wd;
            adst[j] = sm4 + (ql * 8 + bm) * 64 + wd;
        }
        {
            int chunk = u >> 5, wd = u & 31;
            int bn = chunk >> 1, ql = chunk & 1;
            bsrc[j] = B16 + ((size_t)((bcol >> 3) + bn) * Qa + ql) * 32 + wd;
            bdst[j] = sm4 + 1024 + (ql * 16 + bn) * 32 + wd;
        }
    }

    const int ac = tid & 7;
    const int ar0 = tid >> 3;
    const int acsw = ac ^ (ar0 & 7);
    const float* asrc32[4];
    uint4* adst32[4];
    int aokb[4];
    if (a32) {
#pragma unroll
        for (int j = 0; j < 4; j++) {
            int row = ar0 + 32 * j;
            int rowg = brow + row;
            aokb[j] = (rowg < M) ? 16 : 0;
            asrc32[j] = Afp + (size_t)((rowg < M) ? rowg : 0) * K + ac * 4;
            adst32[j] = sm4 + row * 8 + acsw;
        }
    }

    float acc[2][8][4];
#pragma unroll
    for (int mt = 0; mt < 2; mt++)
#pragma unroll
        for (int nt = 0; nt < 8; nt++)
#pragma unroll
            for (int q = 0; q < 4; q++) acc[mt][nt][q] = 0.0f;

    const int S = Qa >> 1;

    if (a32) {
#pragma unroll
        for (int j = 0; j < 4; j++) cpa16(adst32[j], asrc32[j], aokb[j]);
    } else {
#pragma unroll
        for (int j = 0; j < 4; j++) cpa16f(adst[j], asrc[j]);
    }
#pragma unroll
    for (int j = 0; j < 4; j++) cpa16f(bdst[j], bsrc[j]);
    cp_commit();

    for (int s = 0; s < S; s++) {
        const int st = s & 1;
        cp_wait0();
        __syncthreads();
        if (s + 1 < S) {
            const int st2 = st ^ 1;
            if (a32) {
#pragma unroll
                for (int j = 0; j < 4; j++)
                    cpa16(adst32[j] + st2 * 2048, asrc32[j] + (size_t)(s + 1) * 32, aokb[j]);
            } else {
#pragma unroll
                for (int j = 0; j < 4; j++)
                    cpa16f(adst[j] + st2 * 2048, asrc[j] + (size_t)(s + 1) * 128);
            }
#pragma unroll
            for (int j = 0; j < 4; j++)
                cpa16f(bdst[j] + st2 * 2048, bsrc[j] + (size_t)(s + 1) * 64);
        }
        cp_commit();

#pragma unroll
        for (int ql = 0; ql < 2; ql++) {
            uint4 ah[2], al[2];
            if (a32) {
                const float* As = (const float*)(sm4 + st * 2048);
#pragma unroll
                for (int mt = 0; mt < 2; mt++) {
                    const int r = wm + mt * 16 + g;
                    const int rb = r * 32;
                    const int c1 = ((ql * 4) | (t >> 1)) ^ g;
                    const int c2 = c1 ^ 2;
                    const int hw = (t & 1) * 2;
                    float2 f0 = *(const float2*)(As + rb + c1 * 4 + hw);
                    float2 f1 = *(const float2*)(As + rb + 256 + c1 * 4 + hw);
                    float2 f2 = *(const float2*)(As + rb + c2 * 4 + hw);
                    float2 f3 = *(const float2*)(As + rb + 256 + c2 * 4 + hw);
                    packhl(f0.x, f0.y, ah[mt].x, al[mt].x);
                    packhl(f1.x, f1.y, ah[mt].y, al[mt].y);
                    packhl(f2.x, f2.y, ah[mt].z, al[mt].z);
                    packhl(f3.x, f3.y, ah[mt].w, al[mt].w);
                }
            } else {
#pragma unroll
                for (int mt = 0; mt < 2; mt++) {
                    const uint4* ap = sm4 + st * 2048 + (ql * 8 + (wm >> 4) + mt) * 64;
                    ah[mt] = ap[lane];
                    al[mt] = ap[32 + lane];
                }
            }
#pragma unroll
            for (int nt = 0; nt < 8; nt++) {
                uint4 bv = sm4[st * 2048 + 1024 + (ql * 16 + (wn >> 3) + nt) * 32 + lane];
#pragma unroll
                for (int mt = 0; mt < 2; mt++) {
                    mma16(acc[mt][nt], (const uint32_t*)&ah[mt], bv.x, bv.y);
                    mma16(acc[mt][nt], (const uint32_t*)&ah[mt], bv.z, bv.w);
                    mma16(acc[mt][nt], (const uint32_t*)&al[mt], bv.x, bv.y);
                }
            }
        }
    }

    const bool do_stats = (stat != nullptr);
    float csum[16], csq[16];
    if (do_stats) {
#pragma unroll
        for (int i = 0; i < 16; i++) { csum[i] = 0.f; csq[i] = 0.f; }
    }

#pragma unroll
    for (int mt = 0; mt < 2; mt++) {
        const int r0 = brow + wm + mt * 16 + g;
        const int r1 = r0 + 8;
#pragma unroll
        for (int j = 0; j < 4; j++) {
            float v[2][4];
#pragma unroll
            for (int e = 0; e < 2; e++) {
                const int nt = j * 2 + e;
                const int col = bcol + wn + nt * 8 + t * 2;
                const float b0 = bias[col];
                const float b1 = bias[col + 1];
                float x0 = acc[mt][nt][0] + b0;
                float x1 = acc[mt][nt][1] + b1;
                float x2 = acc[mt][nt][2] + b0;
                float x3 = acc[mt][nt][3] + b1;
                if (act) {
                    x0 = softplus_f(x0); x1 = softplus_f(x1);
                    x2 = softplus_f(x2); x3 = softplus_f(x3);
                }
                if (r0 >= M) { x0 = 0.f; x1 = 0.f; }
                if (r1 >= M) { x2 = 0.f; x3 = 0.f; }
                v[e][0] = x0; v[e][1] = x1; v[e][2] = x2; v[e][3] = x3;
                if (C) {
                    if (r0 < M) *(float2*)&C[(size_t)r0 * Nc + col] = make_float2(x0, x1);
                    if (r1 < M) *(float2*)&C[(size_t)r1 * Nc + col] = make_float2(x2, x3);
                }
                if (do_stats) {
                    csum[nt * 2] += x0 + x2;
                    csq[nt * 2] += x0 * x0 + x2 * x2;
                    csum[nt * 2 + 1] += x1 + x3;
                    csq[nt * 2 + 1] += x1 * x1 + x3 * x3;
                }
            }
            if (O16) {
                uint4 hi, lo;
                packhl(v[0][0], v[0][1], hi.x, lo.x);
                packhl(v[0][2], v[0][3], hi.y, lo.y);
                packhl(v[1][0], v[1][1], hi.z, lo.z);
                packhl(v[1][2], v[1][3], hi.w, lo.w);
                size_t chunk = (size_t)((brow + wm + mt * 16) >> 4) * Qout +
                               ((bcol + wn) >> 4) + j;
                O16[chunk * 64 + lane] = hi;
                O16[chunk * 64 + 32 + lane] = lo;
            }
        }
    }

    if (do_stats) {
#pragma unroll
        for (int i = 0; i < 16; i++) {
            float sv = csum[i], qv = csq[i];
            sv += __shfl_xor_sync(0xffffffffu, sv, 4);
            sv += __shfl_xor_sync(0xffffffffu, sv, 8);
            sv += __shfl_xor_sync(0xffffffffu, sv, 16);
            qv += __shfl_xor_sync(0xffffffffu, qv, 4);
            qv += __shfl_xor_sync(0xffffffffu, qv, 8);
            qv += __shfl_xor_sync(0xffffffffu, qv, 16);
            if (g == 0) {
                const int col = bcol + wn + (i >> 1) * 8 + t * 2 + (i & 1);
                red_add_f32(&stat[col], sv);
                red_add_f32(&stat[Nc + col], qv);
            }
        }

        // ---- last-block BN finalize: ab = (gamma/sqrt(var), beta - mean*...) ----
        __threadfence();
        __syncthreads();
        if (tid == 0)
            s_last = (atomicAdd(ctr, 1) == (int)(gridDim.x * gridDim.y) - 1) ? 1 : 0;
        __syncthreads();
        if (s_last) {
            __threadfence();
            // block has 256 threads == DD channels (Nc == DD for stats GEMM)
            float mean = stat[tid] * (1.0f / NN);
            float var = stat[Nc + tid] * (1.0f / NN) - mean * mean;
            float inv = rsqrtf(var + BN_EPS);
            float a = gammap[tid] * inv;
            abp[tid] = a;
            abp[DD + tid] = betap[tid] - mean * a;
            stat[tid] = 0.0f;
            stat[Nc + tid] = 0.0f;
            if (tid == 0) *ctr = 0;
        }
    }
}

// ---------------- non-GEMM kernels ----------------
__global__ void init_h_kernel(const int* __restrict__ atomics,
                              const float* __restrict__ pos,
                              const float* __restrict__ emb1,
                              const float* __restrict__ w2,
                              const float* __restrict__ b2,
                              float* __restrict__ h) {
    size_t idx = (size_t)blockIdx.x * blockDim.x + threadIdx.x;
    if (idx >= (size_t)NN * DD) return;
    int i = (int)(idx / DD);
    int d = (int)(idx & (DD - 1));
    float p0 = pos[i * 3 + 0], p1 = pos[i * 3 + 1], p2 = pos[i * 3 + 2];
    float v = emb1[(size_t)atomics[i] * DD + d];
    v += p0 * w2[d] + p1 * w2[DD + d] + p2 * w2[2 * DD + d] + b2[d];
    h[idx] = v;
}

__global__ void bn_apply_kernel(float* __restrict__ h, const float* __restrict__ ab,
                                int act) {
    size_t idx = (size_t)blockIdx.x * blockDim.x + threadIdx.x;
    if (idx >= (size_t)NN * DD / 4) return;
    int d4 = (int)(idx & (DD / 4 - 1)) * 4;
    float4 v = *((float4*)h + idx);
    float4 a = *(const float4*)(ab + d4);
    float4 b = *(const float4*)(ab + DD + d4);
    v.x = v.x * a.x + b.x;
    v.y = v.y * a.y + b.y;
    v.z = v.z * a.z + b.z;
    v.w = v.w * a.w + b.w;
    if (act) {
        v.x = softplus_f(v.x);
        v.y = softplus_f(v.y);
        v.z = softplus_f(v.z);
        v.w = softplus_f(v.w);
    }
    *((float4*)h + idx) = v;
}

__global__ void pool_count_kernel(const int* __restrict__ batch, float* __restrict__ cnt) {
    int i = blockIdx.x * blockDim.x + threadIdx.x;
    if (i >= NN) return;
    atomicAdd(&cnt[batch[i]], 1.0f);
}

__global__ void pool_sum_h_kernel(const float* __restrict__ h,
                                  const int* __restrict__ batch,
                                  float* __restrict__ ssum) {
    size_t idx = (size_t)blockIdx.x * blockDim.x + threadIdx.x;
    const int CH = DD / 4;
    const size_t nchunks = (NN + 7) / 8;
    if (idx >= nchunks * CH) return;
    int f4 = (int)(idx & (CH - 1)) * 4;
    int i0 = (int)(idx / CH) * 8;
    int cur = batch[i0];
    float4 acc = make_float4(0.f, 0.f, 0.f, 0.f);
#pragma unroll
    for (int r = 0; r < 8; r++) {
        int i = i0 + r;
        if (i >= NN) break;
        int b = batch[i];
        if (b != cur) {
            red_add_v4(&ssum[(size_t)cur * DD + f4], acc.x, acc.y, acc.z, acc.w);
            acc = make_float4(0.f, 0.f, 0.f, 0.f);
            cur = b;
        }
        float4 v = *(const float4*)(h + (size_t)i * DD + f4);
        acc.x += v.x; acc.y += v.y; acc.z += v.z; acc.w += v.w;
    }
    red_add_v4(&ssum[(size_t)cur * DD + f4], acc.x, acc.y, acc.z, acc.w);
}

// one block per graph (256 threads = 256 channels): pm = mean*a + b; resets ssum/cnt
__global__ void pm_kernel(float* __restrict__ ssum, float* __restrict__ cnt,
                          const float* __restrict__ ab, float* __restrict__ pm) {
    int g = blockIdx.x;
    int c = threadIdx.x;
    size_t idx = (size_t)g * DD + c;
    float cv = cnt[g];
    float m = ssum[idx] / fmaxf(cv, 1.0f);
    pm[idx] = m * ab[c] + ab[DD + c];
    ssum[idx] = 0.0f;            // self-reset for next graph replay
    __syncthreads();
    if (c == 0) cnt[g] = 0.0f;   // after all reads of cnt[g]
}

__global__ void head_out_kernel(const float* __restrict__ hid, const float* __restrict__ w2,
                                const float* __restrict__ b2, float* __restrict__ out) {
    int g = blockIdx.x * (blockDim.x >> 5) + (threadIdx.x >> 5);
    if (g >= GG) return;
    int lane = threadIdx.x & 31;
    const float* hr = hid + (size_t)g * (FDIM / 2);
    float s = 0.f;
#pragma unroll
    for (int k = lane; k < FDIM / 2; k += 32) s += hr[k] * w2[k];
#pragma unroll
    for (int o = 16; o; o >>= 1) s += __shfl_down_sync(0xffffffffu, s, o);
    if (lane == 0) out[g] = s + b2[0];
}

// ---------------- host launch ----------------
static inline void launch_gemm(const uint4* A16, const float* Afp, const uint4* B16,
                               const float* bias, float* C, uint4* O16, int M, int Mpad,
                               int Qa, int Nc, int act, float* stat, int Qout,
                               const float* gamma, const float* beta, float* abp,
                               int* ctr) {
    dim3 grid(Nc / 128, Mpad / 128);
    gemm_f16<<<grid, 256, GEMM_SMEM_BYTES>>>(A16, Afp, B16, bias, C, O16, M, Qa, Nc, act,
                                             stat, Qout, gamma, beta, abp, ctr);
}

extern "C" void kernel_launch(void* const* d_in, const int* in_sizes, int n_in,
                              void* d_out, int out_size) {
    const int* atomics = (const int*)d_in[0];
    const float* pos = (const float*)d_in[1];
    const int* edge_index = (const int*)d_in[2];
    const int* edge_attr = (const int*)d_in[3];
    const int* batch = (const int*)d_in[4];
    const float* x_emb1 = (const float*)d_in[5];
    const float* x_emb2_w = (const float*)d_in[6];
    const float* x_emb2_b = (const float*)d_in[7];
    const float* edge_emb = (const float*)d_in[8];
    const float* mlp_w1 = (const float*)d_in[9];
    const float* mlp_b1 = (const float*)d_in[10];
    const float* mlp_w2 = (const float*)d_in[11];
    const float* mlp_b2 = (const float*)d_in[12];
    const float* bn_gamma = (const float*)d_in[13];
    const float* bn_beta = (const float*)d_in[14];
    const float* feat_w = (const float*)d_in[15];
    const float* feat_b = (const float*)d_in[16];
    const float* head_w1 = (const float*)d_in[17];
    const float* head_b1 = (const float*)d_in[18];
    const float* head_w2 = (const float*)d_in[19];
    const float* head_b2 = (const float*)d_in[20];
    float* out = (float*)d_out;

    float *h, *agg, *stat, *ab, *ssum, *cnt, *pm, *gfeat, *hid;
    uint4 *a16b, *w16;
    int *deg, *fill, *rs, *bsum, *srcs, *attrs, *ctr;
    cudaGetSymbolAddress((void**)&h, g_h);
    cudaGetSymbolAddress((void**)&agg, g_agg);
    cudaGetSymbolAddress((void**)&stat, g_stat);
    cudaGetSymbolAddress((void**)&ab, g_ab);
    cudaGetSymbolAddress((void**)&ssum, g_ssum);
    cudaGetSymbolAddress((void**)&cnt, g_cnt);
    cudaGetSymbolAddress((void**)&pm, g_pm);
    cudaGetSymbolAddress((void**)&gfeat, g_gfeat);
    cudaGetSymbolAddress((void**)&hid, g_hid);
    cudaGetSymbolAddress((void**)&a16b, g_a16b);
    cudaGetSymbolAddress((void**)&w16, g_w16);
    cudaGetSymbolAddress((void**)&deg, g_deg);
    cudaGetSymbolAddress((void**)&fill, g_fill);
    cudaGetSymbolAddress((void**)&rs, g_rs);
    cudaGetSymbolAddress((void**)&bsum, g_bsum);
    cudaGetSymbolAddress((void**)&srcs, g_srcs);
    cudaGetSymbolAddress((void**)&attrs, g_attrs);
    cudaGetSymbolAddress((void**)&ctr, g_ctr);

    cudaFuncSetAttribute(gemm_f16, cudaFuncAttributeMaxDynamicSharedMemorySize,
                         GEMM_SMEM_BYTES);

    const size_t ND = (size_t)NN * DD;
    const size_t ND4 = ND / 4;
    const int EL = 256;

    // ---- CSR build ----
    csr_zero<<<(NN + EL - 1) / EL, EL>>>(deg, fill);
    csr_count<<<(EE + EL - 1) / EL, EL>>>(edge_index, deg);
    csr_scan1<<<NB_SCAN, 256>>>(deg, rs, bsum);
    csr_scan2<<<1, 512>>>(bsum);
    csr_scan3<<<NB_SCAN, 256>>>(rs, bsum);
    csr_place<<<(EE + EL - 1) / EL, EL>>>(edge_index, edge_attr, rs, fill, srcs, attrs);

    // ---- B16 prep (batched) ----
    conv_b16<<<640, 256>>>(mlp_w1, w16, DD, 2 * DD, LL);                 // 5x1024 chunks
    conv_b16<<<640, 256>>>(mlp_w2, w16 + 163840, 2 * DD, DD, LL);
    conv_b16<<<128, 256>>>(feat_w, w16 + 327680, DD, FDIM, 1);
    conv_b16<<<128, 256>>>(head_w1, w16 + 360448, FDIM, FDIM / 2, 1);

    init_h_kernel<<<(unsigned)((ND + EL - 1) / EL), EL>>>(atomics, pos, x_emb1, x_emb2_w,
                                                          x_emb2_b, h);

    for (int l = 0; l < LL; l++) {
        const float* emb_l = edge_emb + (size_t)l * NUM_BOND_C * DD;

        gather_edges_kernel<<<(NN + 7) / 8, 256>>>(h, srcs, attrs, rs, emb_l, agg);

        // tmp16 = softplus(agg @ W1 + b1)  [N,512] fragment out (fp32 A)
        launch_gemm(nullptr, agg, w16 + l * 32768, mlp_b1 + (size_t)l * 2 * DD, nullptr,
                    a16b, NN, MPAD_N, DD / 16, 2 * DD, 1, nullptr, FDIM / 16,
                    nullptr, nullptr, nullptr, nullptr);

        // h = tmp16 @ W2 + b2 (+BN stats + last-block finalize -> ab)
        launch_gemm(a16b, nullptr, w16 + 163840 + l * 32768, mlp_b2 + (size_t)l * DD, h,
                    nullptr, NN, MPAD_N, FDIM / 16, DD, 0, stat, 1,
                    bn_gamma + (size_t)l * DD, bn_beta + (size_t)l * DD, ab, ctr);

        if (l < LL - 1) {
            bn_apply_kernel<<<(unsigned)((ND4 + EL - 1) / EL), EL>>>(h, ab, 1);
        }
        // l == LL-1: BN affine commutes with mean pooling; applied in pm_kernel.
    }

    // ---- pool raw h, apply BN affine to pooled means ----
    pool_count_kernel<<<(NN + EL - 1) / EL, EL>>>(batch, cnt);
    {
        size_t total = ((NN + 7) / 8) * (size_t)(DD / 4);
        pool_sum_h_kernel<<<(unsigned)((total + EL - 1) / EL), EL>>>(h, batch, ssum);
    }
    pm_kernel<<<GG, 256>>>(ssum, cnt, ab, pm);

    // gfeat = pm @ feat_w + feat_b
    launch_gemm(nullptr, pm, w16 + 327680, feat_b, gfeat, nullptr, GG, MPAD_G, DD / 16,
                FDIM, 0, nullptr, 1, nullptr, nullptr, nullptr, nullptr);

    // head
    launch_gemm(nullptr, gfeat, w16 + 360448, head_b1, hid, nullptr, GG, MPAD_G, FDIM / 16,
                FDIM / 2, 1, nullptr, 1, nullptr, nullptr, nullptr, nullptr);
    head_out_kernel<<<(GG + 7) / 8, 256>>>(hid, head_w2, head_b2, out);
}

// round 16
// speedup vs baseline: 1.0679x; 1.0679x over previous
#include <cuda_runtime.h>
#include <cuda_fp16.h>
#include <math.h>
#include <stdint.h>

#define NN 100000
#define EE 300000
#define DD 256
#define FDIM 512
#define LL 5
#define GG 4000
#define NUM_BOND_C 2
#define BN_EPS 1e-5f
#define MPAD_N 100096   // 782*128
#define MPAD_G 4096     // 32*128
#define NB_SCAN 391     // ceil(NN/256)

// ---------------- scratch (device globals: no allocation allowed) ----------------
__device__ float g_h[(size_t)NN * DD];
__device__ float g_agg[(size_t)NN * DD];
__device__ float g_stat[2 * DD];
__device__ float g_ab[2 * DD];
__device__ float g_ssum[(size_t)GG * DD];   // zero-init; self-reset by pm_kernel
__device__ float g_cnt[GG];                 // zero-init; self-reset by pm_kernel
__device__ float g_pm[(size_t)GG * DD];
__device__ float g_gfeat[(size_t)GG * FDIM];
__device__ float g_hid[(size_t)GG * (FDIM / 2)];
__device__ uint4 g_a16b[(size_t)(MPAD_N / 16) * (FDIM / 16) * 64];
__device__ uint4 g_w16[393216];
// CSR (by destination)
__device__ int g_deg[NN];
__device__ int g_fill[NN];
__device__ int g_rs[NN + 1];
__device__ int g_bsum[512];
__device__ int g_srcs[EE];
__device__ int g_attrs[EE];

__device__ __forceinline__ float softplus_f(float x) {
    return fmaxf(x, 0.0f) + log1pf(expf(-fabsf(x)));
}

__device__ __forceinline__ void red_add_f32(float* p, float v) {
    asm volatile("red.global.add.f32 [%0], %1;" :: "l"(p), "f"(v) : "memory");
}
__device__ __forceinline__ void red_add_v4(float* p, float x, float y, float z, float w) {
    asm volatile("red.global.add.v4.f32 [%0], {%1,%2,%3,%4};"
                 :: "l"(p), "f"(x), "f"(y), "f"(z), "f"(w) : "memory");
}

// ---------------- fp16 split helpers ----------------
__device__ __forceinline__ void packhl(float x, float y, uint32_t& hi, uint32_t& lo) {
    __half2 h = __floats2half2_rn(x, y);
    float2 hf = __half22float2(h);
    __half2 l = __floats2half2_rn(x - hf.x, y - hf.y);
    hi = *reinterpret_cast<uint32_t*>(&h);
    lo = *reinterpret_cast<uint32_t*>(&l);
}

__device__ __forceinline__ void mma16(float* c, const uint32_t* a, uint32_t b0, uint32_t b1) {
    asm volatile(
        "mma.sync.aligned.m16n8k16.row.col.f32.f16.f16.f32 "
        "{%0,%1,%2,%3},{%4,%5,%6,%7},{%8,%9},{%0,%1,%2,%3};"
        : "+f"(c[0]), "+f"(c[1]), "+f"(c[2]), "+f"(c[3])
        : "r"(a[0]), "r"(a[1]), "r"(a[2]), "r"(a[3]), "r"(b0), "r"(b1));
}

__device__ __forceinline__ void cpa16(void* dst, const void* src, int srcBytes) {
    uint32_t d = (uint32_t)__cvta_generic_to_shared(dst);
    asm volatile("cp.async.cg.shared.global [%0], [%1], 16, %2;"
                 :: "r"(d), "l"(src), "r"(srcBytes) : "memory");
}
__device__ __forceinline__ void cpa16f(void* dst, const void* src) {
    uint32_t d = (uint32_t)__cvta_generic_to_shared(dst);
    asm volatile("cp.async.cg.shared.global [%0], [%1], 16;" :: "r"(d), "l"(src) : "memory");
}
__device__ __forceinline__ void cp_commit() {
    asm volatile("cp.async.commit_group;" ::: "memory");
}
__device__ __forceinline__ void cp_wait0() {
    asm volatile("cp.async.wait_group 0;" ::: "memory");
}

// ---------------- CSR build ----------------
__global__ void csr_zero(int* deg, int* fill) {
    int i = blockIdx.x * blockDim.x + threadIdx.x;
    if (i < NN) { deg[i] = 0; fill[i] = 0; }
}
__global__ void csr_count(const int* __restrict__ edge_index, int* __restrict__ deg) {
    int e = blockIdx.x * blockDim.x + threadIdx.x;
    if (e < EE) atomicAdd(&deg[edge_index[EE + e]], 1);
}
__global__ void csr_scan1(const int* __restrict__ deg, int* __restrict__ rs,
                          int* __restrict__ bsum) {
    __shared__ int sm[256];
    int tid = threadIdx.x;
    int i = blockIdx.x * 256 + tid;
    int v = (i < NN) ? deg[i] : 0;
    sm[tid] = v;
    __syncthreads();
#pragma unroll
    for (int o = 1; o < 256; o <<= 1) {
        int t = (tid >= o) ? sm[tid - o] : 0;
        __syncthreads();
        if (tid >= o) sm[tid] += t;
        __syncthreads();
    }
    if (i < NN) rs[i] = sm[tid] - v;
    if (tid == 255) bsum[blockIdx.x] = sm[255];
}
__global__ void csr_scan2(int* __restrict__ bsum) {
    __shared__ int sm[512];
    int tid = threadIdx.x;
    int v = (tid < NB_SCAN) ? bsum[tid] : 0;
    sm[tid] = v;
    __syncthreads();
#pragma unroll
    for (int o = 1; o < 512; o <<= 1) {
        int t = (tid >= o) ? sm[tid - o] : 0;
        __syncthreads();
        if (tid >= o) sm[tid] += t;
        __syncthreads();
    }
    if (tid < NB_SCAN) bsum[tid] = sm[tid] - v;
}
__global__ void csr_scan3(int* __restrict__ rs, const int* __restrict__ bsum) {
    int i = blockIdx.x * 256 + threadIdx.x;
    if (i < NN) rs[i] += bsum[blockIdx.x];
    if (i == 0) rs[NN] = EE;
}
__global__ void csr_place(const int* __restrict__ edge_index,
                          const int* __restrict__ edge_attr,
                          const int* __restrict__ rs, int* __restrict__ fill,
                          int* __restrict__ srcs, int* __restrict__ attrs) {
    int e = blockIdx.x * blockDim.x + threadIdx.x;
    if (e >= EE) return;
    int d = edge_index[EE + e];
    int p = rs[d] + atomicAdd(&fill[d], 1);
    srcs[p] = edge_index[e];
    attrs[p] = edge_attr[e];
}

// ---------------- gather ----------------
__global__ void gather_edges_kernel(const float* __restrict__ h,
                                    const int* __restrict__ srcs,
                                    const int* __restrict__ attrs,
                                    const int* __restrict__ rs,
                                    const float* __restrict__ emb,
                                    float* __restrict__ agg) {
    int node = blockIdx.x * (blockDim.x >> 5) + (threadIdx.x >> 5);
    if (node >= NN) return;
    int lane = threadIdx.x & 31;
    int c0 = lane * 4, c1 = c0 + 128;
    const float* hn = h + (size_t)node * DD;
    const float* es = emb + (size_t)(NUM_BOND_C - 1) * DD;
    float4 v0 = *(const float4*)(hn + c0);
    float4 v1 = *(const float4*)(hn + c1);
    float4 e0 = *(const float4*)(es + c0);
    float4 e1 = *(const float4*)(es + c1);
    float4 a0 = make_float4(v0.x + e0.x, v0.y + e0.y, v0.z + e0.z, v0.w + e0.w);
    float4 a1 = make_float4(v1.x + e1.x, v1.y + e1.y, v1.z + e1.z, v1.w + e1.w);
    int p0 = rs[node], p1 = rs[node + 1];
    for (int p = p0; p < p1; p++) {
        int s = srcs[p], a = attrs[p];
        const float* hs = h + (size_t)s * DD;
        const float* eb = emb + (size_t)a * DD;
        float4 h0 = *(const float4*)(hs + c0);
        float4 h1 = *(const float4*)(hs + c1);
        float4 b0 = *(const float4*)(eb + c0);
        float4 b1 = *(const float4*)(eb + c1);
        a0.x += h0.x + b0.x; a0.y += h0.y + b0.y; a0.z += h0.z + b0.z; a0.w += h0.w + b0.w;
        a1.x += h1.x + b1.x; a1.y += h1.y + b1.y; a1.z += h1.z + b1.z; a1.w += h1.w + b1.w;
    }
    float* ag = agg + (size_t)node * DD;
    *(float4*)(ag + c0) = a0;
    *(float4*)(ag + c1) = a1;
}

// ---------------- B16 converter (batched over L weight slices) ----------------
__global__ void conv_b16(const float* __restrict__ W, uint4* __restrict__ dst, int K, int N,
                         int L) {
    int Q = K >> 4;
    int per = (N >> 3) * Q;
    int wid = blockIdx.x * (blockDim.x >> 5) + (threadIdx.x >> 5);
    if (wid >= per * L) return;
    int l = wid / per;
    int r = wid - l * per;
    const float* Wl = W + (size_t)l * K * N;
    uint4* dl = dst + (size_t)l * per * 32;
    int bn = r / Q, q = r - bn * Q;
    int lane = threadIdx.x & 31, g = lane >> 2, t = lane & 3;
    int n = bn * 8 + g;
    int k0 = q * 16 + 2 * t, k1 = k0 + 8;
    uint4 v;
    uint32_t l0, l1;
    packhl(Wl[(size_t)k0 * N + n], Wl[(size_t)(k0 + 1) * N + n], v.x, l0);
    packhl(Wl[(size_t)k1 * N + n], Wl[(size_t)(k1 + 1) * N + n], v.y, l1);
    v.z = l0;
    v.w = l1;
    dl[(size_t)r * 32 + lane] = v;
}

// ---------------- fp16x3 tensor-core GEMM (exact R12 config) ----------------
#define GEMM_SMEM_BYTES 65536

__global__ __launch_bounds__(256, 2)
void gemm_f16(const uint4* __restrict__ A16, const float* __restrict__ Afp,
              const uint4* __restrict__ B16, const float* __restrict__ bias,
              float* __restrict__ C, uint4* __restrict__ O16, int M, int Qa, int Nc,
              int act, float* __restrict__ stat, int Qout) {
    extern __shared__ uint4 sm4[];
    const int tid = threadIdx.x, lane = tid & 31, w = tid >> 5;
    const int g = lane >> 2, t = lane & 3;
    const int wm = (w >> 1) * 32, wn = (w & 1) * 64;
    const int brow = blockIdx.y * 128, bcol = blockIdx.x * 128;
    const bool a32 = (Afp != nullptr);
    const int K = Qa << 4;

    const uint4* asrc[4];
    uint4* adst[4];
    const uint4* bsrc[4];
    uint4* bdst[4];
#pragma unroll
    for (int j = 0; j < 4; j++) {
        int u = tid + j * 256;
        {
            int chunk = u >> 6, wd = u & 63;
            int bm = chunk >> 1, ql = chunk & 1;
            asrc[j] = A16 + ((size_t)((brow >> 4) + bm) * Qa + ql) * 64 + wd;
            adst[j] = sm4 + (ql * 8 + bm) * 64 + wd;
        }
        {
            int chunk = u >> 5, wd = u & 31;
            int bn = chunk >> 1, ql = chunk & 1;
            bsrc[j] = B16 + ((size_t)((bcol >> 3) + bn) * Qa + ql) * 32 + wd;
            bdst[j] = sm4 + 1024 + (ql * 16 + bn) * 32 + wd;
        }
    }

    const int ac = tid & 7;
    const int ar0 = tid >> 3;
    const int acsw = ac ^ (ar0 & 7);
    const float* asrc32[4];
    uint4* adst32[4];
    int aokb[4];
    if (a32) {
#pragma unroll
        for (int j = 0; j < 4; j++) {
            int row = ar0 + 32 * j;
            int rowg = brow + row;
            aokb[j] = (rowg < M) ? 16 : 0;
            asrc32[j] = Afp + (size_t)((rowg < M) ? rowg : 0) * K + ac * 4;
            adst32[j] = sm4 + row * 8 + acsw;
        }
    }

    float acc[2][8][4];
#pragma unroll
    for (int mt = 0; mt < 2; mt++)
#pragma unroll
        for (int nt = 0; nt < 8; nt++)
#pragma unroll
            for (int q = 0; q < 4; q++) acc[mt][nt][q] = 0.0f;

    const int S = Qa >> 1;

    if (a32) {
#pragma unroll
        for (int j = 0; j < 4; j++) cpa16(adst32[j], asrc32[j], aokb[j]);
    } else {
#pragma unroll
        for (int j = 0; j < 4; j++) cpa16f(adst[j], asrc[j]);
    }
#pragma unroll
    for (int j = 0; j < 4; j++) cpa16f(bdst[j], bsrc[j]);
    cp_commit();

    for (int s = 0; s < S; s++) {
        const int st = s & 1;
        cp_wait0();
        __syncthreads();
        if (s + 1 < S) {
            const int st2 = st ^ 1;
            if (a32) {
#pragma unroll
                for (int j = 0; j < 4; j++)
                    cpa16(adst32[j] + st2 * 2048, asrc32[j] + (size_t)(s + 1) * 32, aokb[j]);
            } else {
#pragma unroll
                for (int j = 0; j < 4; j++)
                    cpa16f(adst[j] + st2 * 2048, asrc[j] + (size_t)(s + 1) * 128);
            }
#pragma unroll
            for (int j = 0; j < 4; j++)
                cpa16f(bdst[j] + st2 * 2048, bsrc[j] + (size_t)(s + 1) * 64);
        }
        cp_commit();

#pragma unroll
        for (int ql = 0; ql < 2; ql++) {
            uint4 ah[2], al[2];
            if (a32) {
                const float* As = (const float*)(sm4 + st * 2048);
#pragma unroll
                for (int mt = 0; mt < 2; mt++) {
                    const int r = wm + mt * 16 + g;
                    const int rb = r * 32;
                    const int c1 = ((ql * 4) | (t >> 1)) ^ g;
                    const int c2 = c1 ^ 2;
                    const int hw = (t & 1) * 2;
                    float2 f0 = *(const float2*)(As + rb + c1 * 4 + hw);
                    float2 f1 = *(const float2*)(As + rb + 256 + c1 * 4 + hw);
                    float2 f2 = *(const float2*)(As + rb + c2 * 4 + hw);
                    float2 f3 = *(const float2*)(As + rb + 256 + c2 * 4 + hw);
                    packhl(f0.x, f0.y, ah[mt].x, al[mt].x);
                    packhl(f1.x, f1.y, ah[mt].y, al[mt].y);
                    packhl(f2.x, f2.y, ah[mt].z, al[mt].z);
                    packhl(f3.x, f3.y, ah[mt].w, al[mt].w);
                }
            } else {
#pragma unroll
                for (int mt = 0; mt < 2; mt++) {
                    const uint4* ap = sm4 + st * 2048 + (ql * 8 + (wm >> 4) + mt) * 64;
                    ah[mt] = ap[lane];
                    al[mt] = ap[32 + lane];
                }
            }
#pragma unroll
            for (int nt = 0; nt < 8; nt++) {
                uint4 bv = sm4[st * 2048 + 1024 + (ql * 16 + (wn >> 3) + nt) * 32 + lane];
#pragma unroll
                for (int mt = 0; mt < 2; mt++) {
                    mma16(acc[mt][nt], (const uint32_t*)&ah[mt], bv.x, bv.y);
                    mma16(acc[mt][nt], (const uint32_t*)&ah[mt], bv.z, bv.w);
                    mma16(acc[mt][nt], (const uint32_t*)&al[mt], bv.x, bv.y);
                }
            }
        }
    }

    const bool do_stats = (stat != nullptr);
    float csum[16], csq[16];
    if (do_stats) {
#pragma unroll
        for (int i = 0; i < 16; i++) { csum[i] = 0.f; csq[i] = 0.f; }
    }

#pragma unroll
    for (int mt = 0; mt < 2; mt++) {
        const int r0 = brow + wm + mt * 16 + g;
        const int r1 = r0 + 8;
#pragma unroll
        for (int j = 0; j < 4; j++) {
            float v[2][4];
#pragma unroll
            for (int e = 0; e < 2; e++) {
                const int nt = j * 2 + e;
                const int col = bcol + wn + nt * 8 + t * 2;
                const float b0 = bias[col];
                const float b1 = bias[col + 1];
                float x0 = acc[mt][nt][0] + b0;
                float x1 = acc[mt][nt][1] + b1;
                float x2 = acc[mt][nt][2] + b0;
                float x3 = acc[mt][nt][3] + b1;
                if (act) {
                    x0 = softplus_f(x0); x1 = softplus_f(x1);
                    x2 = softplus_f(x2); x3 = softplus_f(x3);
                }
                if (r0 >= M) { x0 = 0.f; x1 = 0.f; }
                if (r1 >= M) { x2 = 0.f; x3 = 0.f; }
                v[e][0] = x0; v[e][1] = x1; v[e][2] = x2; v[e][3] = x3;
                if (C) {
                    if (r0 < M) *(float2*)&C[(size_t)r0 * Nc + col] = make_float2(x0, x1);
                    if (r1 < M) *(float2*)&C[(size_t)r1 * Nc + col] = make_float2(x2, x3);
                }
                if (do_stats) {
                    csum[nt * 2] += x0 + x2;
                    csq[nt * 2] += x0 * x0 + x2 * x2;
                    csum[nt * 2 + 1] += x1 + x3;
                    csq[nt * 2 + 1] += x1 * x1 + x3 * x3;
                }
            }
            if (O16) {
                uint4 hi, lo;
                packhl(v[0][0], v[0][1], hi.x, lo.x);
                packhl(v[0][2], v[0][3], hi.y, lo.y);
                packhl(v[1][0], v[1][1], hi.z, lo.z);
                packhl(v[1][2], v[1][3], hi.w, lo.w);
                size_t chunk = (size_t)((brow + wm + mt * 16) >> 4) * Qout +
                               ((bcol + wn) >> 4) + j;
                O16[chunk * 64 + lane] = hi;
                O16[chunk * 64 + 32 + lane] = lo;
            }
        }
    }

    if (do_stats) {
#pragma unroll
        for (int i = 0; i < 16; i++) {
            float sv = csum[i], qv = csq[i];
            sv += __shfl_xor_sync(0xffffffffu, sv, 4);
            sv += __shfl_xor_sync(0xffffffffu, sv, 8);
            sv += __shfl_xor_sync(0xffffffffu, sv, 16);
            qv += __shfl_xor_sync(0xffffffffu, qv, 4);
            qv += __shfl_xor_sync(0xffffffffu, qv, 8);
            qv += __shfl_xor_sync(0xffffffffu, qv, 16);
            if (g == 0) {
                const int col = bcol + wn + (i >> 1) * 8 + t * 2 + (i & 1);
                red_add_f32(&stat[col], sv);
                red_add_f32(&stat[Nc + col], qv);
            }
        }
    }
}

// ---------------- non-GEMM kernels ----------------
__global__ void init_h_kernel(const int* __restrict__ atomics,
                              const float* __restrict__ pos,
                              const float* __restrict__ emb1,
                              const float* __restrict__ w2,
                              const float* __restrict__ b2,
                              float* __restrict__ h) {
    size_t idx = (size_t)blockIdx.x * blockDim.x + threadIdx.x;
    if (idx >= (size_t)NN * DD) return;
    int i = (int)(idx / DD);
    int d = (int)(idx & (DD - 1));
    float p0 = pos[i * 3 + 0], p1 = pos[i * 3 + 1], p2 = pos[i * 3 + 2];
    float v = emb1[(size_t)atomics[i] * DD + d];
    v += p0 * w2[d] + p1 * w2[DD + d] + p2 * w2[2 * DD + d] + b2[d];
    h[idx] = v;
}

__global__ void zero_kernel(float* __restrict__ p, size_t n) {
    size_t idx = (size_t)blockIdx.x * blockDim.x + threadIdx.x;
    if (idx < n) p[idx] = 0.0f;
}

// consume stat -> ab, then zero stat for the next layer
__global__ void bn_finalize_kernel(float* __restrict__ stat,
                                   const float* __restrict__ gamma,
                                   const float* __restrict__ beta,
                                   float* __restrict__ ab) {
    int d = threadIdx.x;
    float mean = stat[d] * (1.0f / NN);
    float var = stat[DD + d] * (1.0f / NN) - mean * mean;
    float inv = rsqrtf(var + BN_EPS);
    float a = gamma[d] * inv;
    ab[d] = a;
    ab[DD + d] = beta[d] - mean * a;
    stat[d] = 0.0f;
    stat[DD + d] = 0.0f;
}

__global__ void bn_apply_kernel(float* __restrict__ h, const float* __restrict__ ab,
                                int act) {
    size_t idx = (size_t)blockIdx.x * blockDim.x + threadIdx.x;
    if (idx >= (size_t)NN * DD / 4) return;
    int d4 = (int)(idx & (DD / 4 - 1)) * 4;
    float4 v = *((float4*)h + idx);
    float4 a = *(const float4*)(ab + d4);
    float4 b = *(const float4*)(ab + DD + d4);
    v.x = v.x * a.x + b.x;
    v.y = v.y * a.y + b.y;
    v.z = v.z * a.z + b.z;
    v.w = v.w * a.w + b.w;
    if (act) {
        v.x = softplus_f(v.x);
        v.y = softplus_f(v.y);
        v.z = softplus_f(v.z);
        v.w = softplus_f(v.w);
    }
    *((float4*)h + idx) = v;
}

__global__ void pool_count_kernel(const int* __restrict__ batch, float* __restrict__ cnt) {
    int i = blockIdx.x * blockDim.x + threadIdx.x;
    if (i >= NN) return;
    atomicAdd(&cnt[batch[i]], 1.0f);
}

__global__ void pool_sum_h_kernel(const float* __restrict__ h,
                                  const int* __restrict__ batch,
                                  float* __restrict__ ssum) {
    size_t idx = (size_t)blockIdx.x * blockDim.x + threadIdx.x;
    const int CH = DD / 4;
    const size_t nchunks = (NN + 7) / 8;
    if (idx >= nchunks * CH) return;
    int f4 = (int)(idx & (CH - 1)) * 4;
    int i0 = (int)(idx / CH) * 8;
    int cur = batch[i0];
    float4 acc = make_float4(0.f, 0.f, 0.f, 0.f);
#pragma unroll
    for (int r = 0; r < 8; r++) {
        int i = i0 + r;
        if (i >= NN) break;
        int b = batch[i];
        if (b != cur) {
            red_add_v4(&ssum[(size_t)cur * DD + f4], acc.x, acc.y, acc.z, acc.w);
            acc = make_float4(0.f, 0.f, 0.f, 0.f);
            cur = b;
        }
        float4 v = *(const float4*)(h + (size_t)i * DD + f4);
        acc.x += v.x; acc.y += v.y; acc.z += v.z; acc.w += v.w;
    }
    red_add_v4(&ssum[(size_t)cur * DD + f4], acc.x, acc.y, acc.z, acc.w);
}

// one block per graph (256 threads = 256 channels): pm = mean*a + b; self-resets buffers
__global__ void pm_kernel(float* __restrict__ ssum, float* __restrict__ cnt,
                          const float* __restrict__ ab, float* __restrict__ pm) {
    int g = blockIdx.x;
    int c = threadIdx.x;
    size_t idx = (size_t)g * DD + c;
    float cv = cnt[g];
    float m = ssum[idx] / fmaxf(cv, 1.0f);
    pm[idx] = m * ab[c] + ab[DD + c];
    ssum[idx] = 0.0f;
    __syncthreads();
    if (c == 0) cnt[g] = 0.0f;
}

__global__ void head_out_kernel(const float* __restrict__ hid, const float* __restrict__ w2,
                                const float* __restrict__ b2, float* __restrict__ out) {
    int g = blockIdx.x * (blockDim.x >> 5) + (threadIdx.x >> 5);
    if (g >= GG) return;
    int lane = threadIdx.x & 31;
    const float* hr = hid + (size_t)g * (FDIM / 2);
    float s = 0.f;
#pragma unroll
    for (int k = lane; k < FDIM / 2; k += 32) s += hr[k] * w2[k];
#pragma unroll
    for (int o = 16; o; o >>= 1) s += __shfl_down_sync(0xffffffffu, s, o);
    if (lane == 0) out[g] = s + b2[0];
}

// ---------------- host launch ----------------
static inline void launch_gemm(const uint4* A16, const float* Afp, const uint4* B16,
                               const float* bias, float* C, uint4* O16, int M, int Mpad,
                               int Qa, int Nc, int act, float* stat, int Qout) {
    dim3 grid(Nc / 128, Mpad / 128);
    gemm_f16<<<grid, 256, GEMM_SMEM_BYTES>>>(A16, Afp, B16, bias, C, O16, M, Qa, Nc, act,
                                             stat, Qout);
}

extern "C" void kernel_launch(void* const* d_in, const int* in_sizes, int n_in,
                              void* d_out, int out_size) {
    const int* atomics = (const int*)d_in[0];
    const float* pos = (const float*)d_in[1];
    const int* edge_index = (const int*)d_in[2];
    const int* edge_attr = (const int*)d_in[3];
    const int* batch = (const int*)d_in[4];
    const float* x_emb1 = (const float*)d_in[5];
    const float* x_emb2_w = (const float*)d_in[6];
    const float* x_emb2_b = (const float*)d_in[7];
    const float* edge_emb = (const float*)d_in[8];
    const float* mlp_w1 = (const float*)d_in[9];
    const float* mlp_b1 = (const float*)d_in[10];
    const float* mlp_w2 = (const float*)d_in[11];
    const float* mlp_b2 = (const float*)d_in[12];
    const float* bn_gamma = (const float*)d_in[13];
    const float* bn_beta = (const float*)d_in[14];
    const float* feat_w = (const float*)d_in[15];
    const float* feat_b = (const float*)d_in[16];
    const float* head_w1 = (const float*)d_in[17];
    const float* head_b1 = (const float*)d_in[18];
    const float* head_w2 = (const float*)d_in[19];
    const float* head_b2 = (const float*)d_in[20];
    float* out = (float*)d_out;

    float *h, *agg, *stat, *ab, *ssum, *cnt, *pm, *gfeat, *hid;
    uint4 *a16b, *w16;
    int *deg, *fill, *rs, *bsum, *srcs, *attrs;
    cudaGetSymbolAddress((void**)&h, g_h);
    cudaGetSymbolAddress((void**)&agg, g_agg);
    cudaGetSymbolAddress((void**)&stat, g_stat);
    cudaGetSymbolAddress((void**)&ab, g_ab);
    cudaGetSymbolAddress((void**)&ssum, g_ssum);
    cudaGetSymbolAddress((void**)&cnt, g_cnt);
    cudaGetSymbolAddress((void**)&pm, g_pm);
    cudaGetSymbolAddress((void**)&gfeat, g_gfeat);
    cudaGetSymbolAddress((void**)&hid, g_hid);
    cudaGetSymbolAddress((void**)&a16b, g_a16b);
    cudaGetSymbolAddress((void**)&w16, g_w16);
    cudaGetSymbolAddress((void**)&deg, g_deg);
    cudaGetSymbolAddress((void**)&fill, g_fill);
    cudaGetSymbolAddress((void**)&rs, g_rs);
    cudaGetSymbolAddress((void**)&bsum, g_bsum);
    cudaGetSymbolAddress((void**)&srcs, g_srcs);
    cudaGetSymbolAddress((void**)&attrs, g_attrs);

    cudaFuncSetAttribute(gemm_f16, cudaFuncAttributeMaxDynamicSharedMemorySize,
                         GEMM_SMEM_BYTES);

    const size_t ND = (size_t)NN * DD;
    const size_t ND4 = ND / 4;
    const int EL = 256;

    // ---- CSR build ----
    csr_zero<<<(NN + EL - 1) / EL, EL>>>(deg, fill);
    csr_count<<<(EE + EL - 1) / EL, EL>>>(edge_index, deg);
    csr_scan1<<<NB_SCAN, 256>>>(deg, rs, bsum);
    csr_scan2<<<1, 512>>>(bsum);
    csr_scan3<<<NB_SCAN, 256>>>(rs, bsum);
    csr_place<<<(EE + EL - 1) / EL, EL>>>(edge_index, edge_attr, rs, fill, srcs, attrs);

    // ---- B16 prep (batched: 4 launches) ----
    conv_b16<<<640, 256>>>(mlp_w1, w16, DD, 2 * DD, LL);
    conv_b16<<<640, 256>>>(mlp_w2, w16 + 163840, 2 * DD, DD, LL);
    conv_b16<<<128, 256>>>(feat_w, w16 + 327680, DD, FDIM, 1);
    conv_b16<<<128, 256>>>(head_w1, w16 + 360448, FDIM, FDIM / 2, 1);

    init_h_kernel<<<(unsigned)((ND + EL - 1) / EL), EL>>>(atomics, pos, x_emb1, x_emb2_w,
                                                          x_emb2_b, h);
    zero_kernel<<<1, 512>>>(stat, 2 * DD);   // once; bn_finalize re-zeroes per layer

    for (int l = 0; l < LL; l++) {
        const float* emb_l = edge_emb + (size_t)l * NUM_BOND_C * DD;

        gather_edges_kernel<<<(NN + 7) / 8, 256>>>(h, srcs, attrs, rs, emb_l, agg);

        launch_gemm(nullptr, agg, w16 + l * 32768, mlp_b1 + (size_t)l * 2 * DD, nullptr,
                    a16b, NN, MPAD_N, DD / 16, 2 * DD, 1, nullptr, FDIM / 16);

        launch_gemm(a16b, nullptr, w16 + 163840 + l * 32768, mlp_b2 + (size_t)l * DD, h,
                    nullptr, NN, MPAD_N, FDIM / 16, DD, 0, stat, 1);

        bn_finalize_kernel<<<1, 256>>>(stat, bn_gamma + (size_t)l * DD,
                                       bn_beta + (size_t)l * DD, ab);

        if (l < LL - 1) {
            bn_apply_kernel<<<(unsigned)((ND4 + EL - 1) / EL), EL>>>(h, ab, 1);
        }
        // l == LL-1: BN affine commutes with mean pooling; applied in pm_kernel.
    }

    // ---- pool raw h, apply BN affine to pooled means ----
    pool_count_kernel<<<(NN + EL - 1) / EL, EL>>>(batch, cnt);
    {
        size_t total = ((NN + 7) / 8) * (size_t)(DD / 4);
        pool_sum_h_kernel<<<(unsigned)((total + EL - 1) / EL), EL>>>(h, batch, ssum);
    }
    pm_kernel<<<GG, 256>>>(ssum, cnt, ab, pm);

    // gfeat = pm @ feat_w + feat_b
    launch_gemm(nullptr, pm, w16 + 327680, feat_b, gfeat, nullptr, GG, MPAD_G, DD / 16,
                FDIM, 0, nullptr, 1);

    // head
    launch_gemm(nullptr, gfeat, w16 + 360448, head_b1, hid, nullptr, GG, MPAD_G, FDIM / 16,
                FDIM / 2, 1, nullptr, 1);
    head_out_kernel<<<(GG + 7) / 8, 256>>>(hid, head_w2, head_b2, out);
}

// round 17
// speedup vs baseline: 1.0816x; 1.0128x over previous
#include <cuda_runtime.h>
#include <cuda_fp16.h>
#include <math.h>
#include <stdint.h>

#define NN 100000
#define EE 300000
#define DD 256
#define FDIM 512
#define LL 5
#define GG 4000
#define NUM_BOND_C 2
#define BN_EPS 1e-5f
#define MPAD_N 100096   // 782*128
#define MPAD_G 4096     // 32*128
#define NB_SCAN 391     // ceil(NN/256)

// ---------------- scratch (device globals: no allocation allowed) ----------------
__device__ float g_h[(size_t)NN * DD];
__device__ float g_agg[(size_t)NN * DD];
__device__ float g_stat[2 * DD];
__device__ float g_ab[2 * DD];
__device__ float g_ssum[(size_t)GG * DD];   // zero-init; self-reset by pm_kernel
__device__ float g_cnt[GG];                 // zero-init; self-reset by pm_kernel
__device__ float g_pm[(size_t)GG * DD];
__device__ float g_gfeat[(size_t)GG * FDIM];
__device__ float g_hid[(size_t)GG * (FDIM / 2)];
__device__ uint4 g_a16b[(size_t)(MPAD_N / 16) * (FDIM / 16) * 64];
__device__ uint4 g_w16[393216];
// CSR (by destination)
__device__ int g_deg[NN];
__device__ int g_fill[NN];
__device__ int g_rs[NN + 1];
__device__ int g_bsum[512];
__device__ int g_srcs[EE];
__device__ int g_attrs[EE];

__device__ __forceinline__ float softplus_f(float x) {
    return fmaxf(x, 0.0f) + log1pf(expf(-fabsf(x)));
}

__device__ __forceinline__ void red_add_f32(float* p, float v) {
    asm volatile("red.global.add.f32 [%0], %1;" :: "l"(p), "f"(v) : "memory");
}
__device__ __forceinline__ void red_add_v4(float* p, float x, float y, float z, float w) {
    asm volatile("red.global.add.v4.f32 [%0], {%1,%2,%3,%4};"
                 :: "l"(p), "f"(x), "f"(y), "f"(z), "f"(w) : "memory");
}

// ---------------- fp16 split helpers ----------------
__device__ __forceinline__ void packhl(float x, float y, uint32_t& hi, uint32_t& lo) {
    __half2 h = __floats2half2_rn(x, y);
    float2 hf = __half22float2(h);
    __half2 l = __floats2half2_rn(x - hf.x, y - hf.y);
    hi = *reinterpret_cast<uint32_t*>(&h);
    lo = *reinterpret_cast<uint32_t*>(&l);
}

__device__ __forceinline__ void mma16(float* c, const uint32_t* a, uint32_t b0, uint32_t b1) {
    asm volatile(
        "mma.sync.aligned.m16n8k16.row.col.f32.f16.f16.f32 "
        "{%0,%1,%2,%3},{%4,%5,%6,%7},{%8,%9},{%0,%1,%2,%3};"
        : "+f"(c[0]), "+f"(c[1]), "+f"(c[2]), "+f"(c[3])
        : "r"(a[0]), "r"(a[1]), "r"(a[2]), "r"(a[3]), "r"(b0), "r"(b1));
}

__device__ __forceinline__ void cpa16(void* dst, const void* src, int srcBytes) {
    uint32_t d = (uint32_t)__cvta_generic_to_shared(dst);
    asm volatile("cp.async.cg.shared.global [%0], [%1], 16, %2;"
                 :: "r"(d), "l"(src), "r"(srcBytes) : "memory");
}
__device__ __forceinline__ void cpa16f(void* dst, const void* src) {
    uint32_t d = (uint32_t)__cvta_generic_to_shared(dst);
    asm volatile("cp.async.cg.shared.global [%0], [%1], 16;" :: "r"(d), "l"(src) : "memory");
}
__device__ __forceinline__ void cp_commit() {
    asm volatile("cp.async.commit_group;" ::: "memory");
}
__device__ __forceinline__ void cp_wait0() {
    asm volatile("cp.async.wait_group 0;" ::: "memory");
}

// ---------------- CSR build ----------------
__global__ void csr_zero(int* deg, int* fill) {
    int i = blockIdx.x * blockDim.x + threadIdx.x;
    if (i < NN) { deg[i] = 0; fill[i] = 0; }
}
__global__ void csr_count(const int* __restrict__ edge_index, int* __restrict__ deg) {
    int e = blockIdx.x * blockDim.x + threadIdx.x;
    if (e < EE) atomicAdd(&deg[edge_index[EE + e]], 1);
}
__global__ void csr_scan1(const int* __restrict__ deg, int* __restrict__ rs,
                          int* __restrict__ bsum) {
    __shared__ int sm[256];
    int tid = threadIdx.x;
    int i = blockIdx.x * 256 + tid;
    int v = (i < NN) ? deg[i] : 0;
    sm[tid] = v;
    __syncthreads();
#pragma unroll
    for (int o = 1; o < 256; o <<= 1) {
        int t = (tid >= o) ? sm[tid - o] : 0;
        __syncthreads();
        if (tid >= o) sm[tid] += t;
        __syncthreads();
    }
    if (i < NN) rs[i] = sm[tid] - v;
    if (tid == 255) bsum[blockIdx.x] = sm[255];
}
__global__ void csr_scan2(int* __restrict__ bsum) {
    __shared__ int sm[512];
    int tid = threadIdx.x;
    int v = (tid < NB_SCAN) ? bsum[tid] : 0;
    sm[tid] = v;
    __syncthreads();
#pragma unroll
    for (int o = 1; o < 512; o <<= 1) {
        int t = (tid >= o) ? sm[tid - o] : 0;
        __syncthreads();
        if (tid >= o) sm[tid] += t;
        __syncthreads();
    }
    if (tid < NB_SCAN) bsum[tid] = sm[tid] - v;
}
__global__ void csr_scan3(int* __restrict__ rs, const int* __restrict__ bsum) {
    int i = blockIdx.x * 256 + threadIdx.x;
    if (i < NN) rs[i] += bsum[blockIdx.x];
    if (i == 0) rs[NN] = EE;
}
__global__ void csr_place(const int* __restrict__ edge_index,
                          const int* __restrict__ edge_attr,
                          const int* __restrict__ rs, int* __restrict__ fill,
                          int* __restrict__ srcs, int* __restrict__ attrs) {
    int e = blockIdx.x * blockDim.x + threadIdx.x;
    if (e >= EE) return;
    int d = edge_index[EE + e];
    int p = rs[d] + atomicAdd(&fill[d], 1);
    srcs[p] = edge_index[e];
    attrs[p] = edge_attr[e];
}

// ---------------- gather (2-edge unrolled: overlapped L2 round trips) -------------
__global__ void gather_edges_kernel(const float* __restrict__ h,
                                    const int* __restrict__ srcs,
                                    const int* __restrict__ attrs,
                                    const int* __restrict__ rs,
                                    const float* __restrict__ emb,
                                    float* __restrict__ agg) {
    int node = blockIdx.x * (blockDim.x >> 5) + (threadIdx.x >> 5);
    if (node >= NN) return;
    int lane = threadIdx.x & 31;
    int c0 = lane * 4, c1 = c0 + 128;
    const float* hn = h + (size_t)node * DD;
    const float* es = emb + (size_t)(NUM_BOND_C - 1) * DD;
    float4 v0 = *(const float4*)(hn + c0);
    float4 v1 = *(const float4*)(hn + c1);
    float4 e0 = *(const float4*)(es + c0);
    float4 e1 = *(const float4*)(es + c1);
    float4 a0 = make_float4(v0.x + e0.x, v0.y + e0.y, v0.z + e0.z, v0.w + e0.w);
    float4 a1 = make_float4(v1.x + e1.x, v1.y + e1.y, v1.z + e1.z, v1.w + e1.w);
    int p0 = rs[node], p1 = rs[node + 1];
    int p = p0;
    for (; p + 2 <= p1; p += 2) {
        int sA = srcs[p], aA = attrs[p];
        int sB = srcs[p + 1], aB = attrs[p + 1];
        const float* hA = h + (size_t)sA * DD;
        const float* hB = h + (size_t)sB * DD;
        const float* eA = emb + (size_t)aA * DD;
        const float* eB = emb + (size_t)aB * DD;
        float4 hA0 = *(const float4*)(hA + c0);
        float4 hA1 = *(const float4*)(hA + c1);
        float4 hB0 = *(const float4*)(hB + c0);
        float4 hB1 = *(const float4*)(hB + c1);
        float4 eA0 = *(const float4*)(eA + c0);
        float4 eA1 = *(const float4*)(eA + c1);
        float4 eB0 = *(const float4*)(eB + c0);
        float4 eB1 = *(const float4*)(eB + c1);
        a0.x += (hA0.x + eA0.x) + (hB0.x + eB0.x);
        a0.y += (hA0.y + eA0.y) + (hB0.y + eB0.y);
        a0.z += (hA0.z + eA0.z) + (hB0.z + eB0.z);
        a0.w += (hA0.w + eA0.w) + (hB0.w + eB0.w);
        a1.x += (hA1.x + eA1.x) + (hB1.x + eB1.x);
        a1.y += (hA1.y + eA1.y) + (hB1.y + eB1.y);
        a1.z += (hA1.z + eA1.z) + (hB1.z + eB1.z);
        a1.w += (hA1.w + eA1.w) + (hB1.w + eB1.w);
    }
    if (p < p1) {
        int s = srcs[p], a = attrs[p];
        const float* hs = h + (size_t)s * DD;
        const float* eb = emb + (size_t)a * DD;
        float4 h0 = *(const float4*)(hs + c0);
        float4 h1 = *(const float4*)(hs + c1);
        float4 b0 = *(const float4*)(eb + c0);
        float4 b1 = *(const float4*)(eb + c1);
        a0.x += h0.x + b0.x; a0.y += h0.y + b0.y; a0.z += h0.z + b0.z; a0.w += h0.w + b0.w;
        a1.x += h1.x + b1.x; a1.y += h1.y + b1.y; a1.z += h1.z + b1.z; a1.w += h1.w + b1.w;
    }
    float* ag = agg + (size_t)node * DD;
    *(float4*)(ag + c0) = a0;
    *(float4*)(ag + c1) = a1;
}

// ---------------- B16 converter (batched over L weight slices) ----------------
__global__ void conv_b16(const float* __restrict__ W, uint4* __restrict__ dst, int K, int N,
                         int L) {
    int Q = K >> 4;
    int per = (N >> 3) * Q;
    int wid = blockIdx.x * (blockDim.x >> 5) + (threadIdx.x >> 5);
    if (wid >= per * L) return;
    int l = wid / per;
    int r = wid - l * per;
    const float* Wl = W + (size_t)l * K * N;
    uint4* dl = dst + (size_t)l * per * 32;
    int bn = r / Q, q = r - bn * Q;
    int lane = threadIdx.x & 31, g = lane >> 2, t = lane & 3;
    int n = bn * 8 + g;
    int k0 = q * 16 + 2 * t, k1 = k0 + 8;
    uint4 v;
    uint32_t l0, l1;
    packhl(Wl[(size_t)k0 * N + n], Wl[(size_t)(k0 + 1) * N + n], v.x, l0);
    packhl(Wl[(size_t)k1 * N + n], Wl[(size_t)(k1 + 1) * N + n], v.y, l1);
    v.z = l0;
    v.w = l1;
    dl[(size_t)r * 32 + lane] = v;
}

// ---------------- fp16x3 tensor-core GEMM (exact R12 config) ----------------
#define GEMM_SMEM_BYTES 65536

__global__ __launch_bounds__(256, 2)
void gemm_f16(const uint4* __restrict__ A16, const float* __restrict__ Afp,
              const uint4* __restrict__ B16, const float* __restrict__ bias,
              float* __restrict__ C, uint4* __restrict__ O16, int M, int Qa, int Nc,
              int act, float* __restrict__ stat, int Qout) {
    extern __shared__ uint4 sm4[];
    const int tid = threadIdx.x, lane = tid & 31, w = tid >> 5;
    const int g = lane >> 2, t = lane & 3;
    const int wm = (w >> 1) * 32, wn = (w & 1) * 64;
    const int brow = blockIdx.y * 128, bcol = blockIdx.x * 128;
    const bool a32 = (Afp != nullptr);
    const int K = Qa << 4;

    const uint4* asrc[4];
    uint4* adst[4];
    const uint4* bsrc[4];
    uint4* bdst[4];
#pragma unroll
    for (int j = 0; j < 4; j++) {
        int u = tid + j * 256;
        {
            int chunk = u >> 6, wd = u & 63;
            int bm = chunk >> 1, ql = chunk & 1;
            asrc[j] = A16 + ((size_t)((brow >> 4) + bm) * Qa + ql) * 64 + wd;
            adst[j] = sm4 + (ql * 8 + bm) * 64 + wd;
        }
        {
            int chunk = u >> 5, wd = u & 31;
            int bn = chunk >> 1, ql = chunk & 1;
            bsrc[j] = B16 + ((size_t)((bcol >> 3) + bn) * Qa + ql) * 32 + wd;
            bdst[j] = sm4 + 1024 + (ql * 16 + bn) * 32 + wd;
        }
    }

    const int ac = tid & 7;
    const int ar0 = tid >> 3;
    const int acsw = ac ^ (ar0 & 7);
    const float* asrc32[4];
    uint4* adst32[4];
    int aokb[4];
    if (a32) {
#pragma unroll
        for (int j = 0; j < 4; j++) {
            int row = ar0 + 32 * j;
            int rowg = brow + row;
            aokb[j] = (rowg < M) ? 16 : 0;
            asrc32[j] = Afp + (size_t)((rowg < M) ? rowg : 0) * K + ac * 4;
            adst32[j] = sm4 + row * 8 + acsw;
        }
    }

    float acc[2][8][4];
#pragma unroll
    for (int mt = 0; mt < 2; mt++)
#pragma unroll
        for (int nt = 0; nt < 8; nt++)
#pragma unroll
            for (int q = 0; q < 4; q++) acc[mt][nt][q] = 0.0f;

    const int S = Qa >> 1;

    if (a32) {
#pragma unroll
        for (int j = 0; j < 4; j++) cpa16(adst32[j], asrc32[j], aokb[j]);
    } else {
#pragma unroll
        for (int j = 0; j < 4; j++) cpa16f(adst[j], asrc[j]);
    }
#pragma unroll
    for (int j = 0; j < 4; j++) cpa16f(bdst[j], bsrc[j]);
    cp_commit();

    for (int s = 0; s < S; s++) {
        const int st = s & 1;
        cp_wait0();
        __syncthreads();
        if (s + 1 < S) {
            const int st2 = st ^ 1;
            if (a32) {
#pragma unroll
                for (int j = 0; j < 4; j++)
                    cpa16(adst32[j] + st2 * 2048, asrc32[j] + (size_t)(s + 1) * 32, aokb[j]);
            } else {
#pragma unroll
                for (int j = 0; j < 4; j++)
                    cpa16f(adst[j] + st2 * 2048, asrc[j] + (size_t)(s + 1) * 128);
            }
#pragma unroll
            for (int j = 0; j < 4; j++)
                cpa16f(bdst[j] + st2 * 2048, bsrc[j] + (size_t)(s + 1) * 64);
        }
        cp_commit();

#pragma unroll
        for (int ql = 0; ql < 2; ql++) {
            uint4 ah[2], al[2];
            if (a32) {
                const float* As = (const float*)(sm4 + st * 2048);
#pragma unroll
                for (int mt = 0; mt < 2; mt++) {
                    const int r = wm + mt * 16 + g;
                    const int rb = r * 32;
                    const int c1 = ((ql * 4) | (t >> 1)) ^ g;
                    const int c2 = c1 ^ 2;
                    const int hw = (t & 1) * 2;
                    float2 f0 = *(const float2*)(As + rb + c1 * 4 + hw);
                    float2 f1 = *(const float2*)(As + rb + 256 + c1 * 4 + hw);
                    float2 f2 = *(const float2*)(As + rb + c2 * 4 + hw);
                    float2 f3 = *(const float2*)(As + rb + 256 + c2 * 4 + hw);
                    packhl(f0.x, f0.y, ah[mt].x, al[mt].x);
                    packhl(f1.x, f1.y, ah[mt].y, al[mt].y);
                    packhl(f2.x, f2.y, ah[mt].z, al[mt].z);
                    packhl(f3.x, f3.y, ah[mt].w, al[mt].w);
                }
            } else {
#pragma unroll
                for (int mt = 0; mt < 2; mt++) {
                    const uint4* ap = sm4 + st * 2048 + (ql * 8 + (wm >> 4) + mt) * 64;
                    ah[mt] = ap[lane];
                    al[mt] = ap[32 + lane];
                }
            }
#pragma unroll
            for (int nt = 0; nt < 8; nt++) {
                uint4 bv = sm4[st * 2048 + 1024 + (ql * 16 + (wn >> 3) + nt) * 32 + lane];
#pragma unroll
                for (int mt = 0; mt < 2; mt++) {
                    mma16(acc[mt][nt], (const uint32_t*)&ah[mt], bv.x, bv.y);
                    mma16(acc[mt][nt], (const uint32_t*)&ah[mt], bv.z, bv.w);
                    mma16(acc[mt][nt], (const uint32_t*)&al[mt], bv.x, bv.y);
                }
            }
        }
    }

    const bool do_stats = (stat != nullptr);
    float csum[16], csq[16];
    if (do_stats) {
#pragma unroll
        for (int i = 0; i < 16; i++) { csum[i] = 0.f; csq[i] = 0.f; }
    }

#pragma unroll
    for (int mt = 0; mt < 2; mt++) {
        const int r0 = brow + wm + mt * 16 + g;
        const int r1 = r0 + 8;
#pragma unroll
        for (int j = 0; j < 4; j++) {
            float v[2][4];
#pragma unroll
            for (int e = 0; e < 2; e++) {
                const int nt = j * 2 + e;
                const int col = bcol + wn + nt * 8 + t * 2;
                const float b0 = bias[col];
                const float b1 = bias[col + 1];
                float x0 = acc[mt][nt][0] + b0;
                float x1 = acc[mt][nt][1] + b1;
                float x2 = acc[mt][nt][2] + b0;
                float x3 = acc[mt][nt][3] + b1;
                if (act) {
                    x0 = softplus_f(x0); x1 = softplus_f(x1);
                    x2 = softplus_f(x2); x3 = softplus_f(x3);
                }
                if (r0 >= M) { x0 = 0.f; x1 = 0.f; }
                if (r1 >= M) { x2 = 0.f; x3 = 0.f; }
                v[e][0] = x0; v[e][1] = x1; v[e][2] = x2; v[e][3] = x3;
                if (C) {
                    if (r0 < M) *(float2*)&C[(size_t)r0 * Nc + col] = make_float2(x0, x1);
                    if (r1 < M) *(float2*)&C[(size_t)r1 * Nc + col] = make_float2(x2, x3);
                }
                if (do_stats) {
                    csum[nt * 2] += x0 + x2;
                    csq[nt * 2] += x0 * x0 + x2 * x2;
                    csum[nt * 2 + 1] += x1 + x3;
                    csq[nt * 2 + 1] += x1 * x1 + x3 * x3;
                }
            }
            if (O16) {
                uint4 hi, lo;
                packhl(v[0][0], v[0][1], hi.x, lo.x);
                packhl(v[0][2], v[0][3], hi.y, lo.y);
                packhl(v[1][0], v[1][1], hi.z, lo.z);
                packhl(v[1][2], v[1][3], hi.w, lo.w);
                size_t chunk = (size_t)((brow + wm + mt * 16) >> 4) * Qout +
                               ((bcol + wn) >> 4) + j;
                O16[chunk * 64 + lane] = hi;
                O16[chunk * 64 + 32 + lane] = lo;
            }
        }
    }

    if (do_stats) {
#pragma unroll
        for (int i = 0; i < 16; i++) {
            float sv = csum[i], qv = csq[i];
            sv += __shfl_xor_sync(0xffffffffu, sv, 4);
            sv += __shfl_xor_sync(0xffffffffu, sv, 8);
            sv += __shfl_xor_sync(0xffffffffu, sv, 16);
            qv += __shfl_xor_sync(0xffffffffu, qv, 4);
            qv += __shfl_xor_sync(0xffffffffu, qv, 8);
            qv += __shfl_xor_sync(0xffffffffu, qv, 16);
            if (g == 0) {
                const int col = bcol + wn + (i >> 1) * 8 + t * 2 + (i & 1);
                red_add_f32(&stat[col], sv);
                red_add_f32(&stat[Nc + col], qv);
            }
        }
    }
}

// ---------------- non-GEMM kernels ----------------
__global__ void init_h_kernel(const int* __restrict__ atomics,
                              const float* __restrict__ pos,
                              const float* __restrict__ emb1,
                              const float* __restrict__ w2,
                              const float* __restrict__ b2,
                              float* __restrict__ h) {
    size_t idx = (size_t)blockIdx.x * blockDim.x + threadIdx.x;
    if (idx >= (size_t)NN * DD) return;
    int i = (int)(idx / DD);
    int d = (int)(idx & (DD - 1));
    float p0 = pos[i * 3 + 0], p1 = pos[i * 3 + 1], p2 = pos[i * 3 + 2];
    float v = emb1[(size_t)atomics[i] * DD + d];
    v += p0 * w2[d] + p1 * w2[DD + d] + p2 * w2[2 * DD + d] + b2[d];
    h[idx] = v;
}

__global__ void zero_kernel(float* __restrict__ p, size_t n) {
    size_t idx = (size_t)blockIdx.x * blockDim.x + threadIdx.x;
    if (idx < n) p[idx] = 0.0f;
}

// consume stat -> ab, then zero stat for the next layer
__global__ void bn_finalize_kernel(float* __restrict__ stat,
                                   const float* __restrict__ gamma,
                                   const float* __restrict__ beta,
                                   float* __restrict__ ab) {
    int d = threadIdx.x;
    float mean = stat[d] * (1.0f / NN);
    float var = stat[DD + d] * (1.0f / NN) - mean * mean;
    float inv = rsqrtf(var + BN_EPS);
    float a = gamma[d] * inv;
    ab[d] = a;
    ab[DD + d] = beta[d] - mean * a;
    stat[d] = 0.0f;
    stat[DD + d] = 0.0f;
}

__global__ void bn_apply_kernel(float* __restrict__ h, const float* __restrict__ ab,
                                int act) {
    size_t idx = (size_t)blockIdx.x * blockDim.x + threadIdx.x;
    if (idx >= (size_t)NN * DD / 4) return;
    int d4 = (int)(idx & (DD / 4 - 1)) * 4;
    float4 v = *((float4*)h + idx);
    float4 a = *(const float4*)(ab + d4);
    float4 b = *(const float4*)(ab + DD + d4);
    v.x = v.x * a.x + b.x;
    v.y = v.y * a.y + b.y;
    v.z = v.z * a.z + b.z;
    v.w = v.w * a.w + b.w;
    if (act) {
        v.x = softplus_f(v.x);
        v.y = softplus_f(v.y);
        v.z = softplus_f(v.z);
        v.w = softplus_f(v.w);
    }
    *((float4*)h + idx) = v;
}

__global__ void pool_count_kernel(const int* __restrict__ batch, float* __restrict__ cnt) {
    int i = blockIdx.x * blockDim.x + threadIdx.x;
    if (i >= NN) return;
    atomicAdd(&cnt[batch[i]], 1.0f);
}

__global__ void pool_sum_h_kernel(const float* __restrict__ h,
                                  const int* __restrict__ batch,
                                  float* __restrict__ ssum) {
    size_t idx = (size_t)blockIdx.x * blockDim.x + threadIdx.x;
    const int CH = DD / 4;
    const size_t nchunks = (NN + 7) / 8;
    if (idx >= nchunks * CH) return;
    int f4 = (int)(idx & (CH - 1)) * 4;
    int i0 = (int)(idx / CH) * 8;
    int cur = batch[i0];
    float4 acc = make_float4(0.f, 0.f, 0.f, 0.f);
#pragma unroll
    for (int r = 0; r < 8; r++) {
        int i = i0 + r;
        if (i >= NN) break;
        int b = batch[i];
        if (b != cur) {
            red_add_v4(&ssum[(size_t)cur * DD + f4], acc.x, acc.y, acc.z, acc.w);
            acc = make_float4(0.f, 0.f, 0.f, 0.f);
            cur = b;
        }
        float4 v = *(const float4*)(h + (size_t)i * DD + f4);
        acc.x += v.x; acc.y += v.y; acc.z += v.z; acc.w += v.w;
    }
    red_add_v4(&ssum[(size_t)cur * DD + f4], acc.x, acc.y, acc.z, acc.w);
}

// one block per graph (256 threads = 256 channels): pm = mean*a + b; self-resets buffers
__global__ void pm_kernel(float* __restrict__ ssum, float* __restrict__ cnt,
                          const float* __restrict__ ab, float* __restrict__ pm) {
    int g = blockIdx.x;
    int c = threadIdx.x;
    size_t idx = (size_t)g * DD + c;
    float cv = cnt[g];
    float m = ssum[idx] / fmaxf(cv, 1.0f);
    pm[idx] = m * ab[c] + ab[DD + c];
    ssum[idx] = 0.0f;
    __syncthreads();
    if (c == 0) cnt[g] = 0.0f;
}

__global__ void head_out_kernel(const float* __restrict__ hid, const float* __restrict__ w2,
                                const float* __restrict__ b2, float* __restrict__ out) {
    int g = blockIdx.x * (blockDim.x >> 5) + (threadIdx.x >> 5);
    if (g >= GG) return;
    int lane = threadIdx.x & 31;
    const float* hr = hid + (size_t)g * (FDIM / 2);
    float s = 0.f;
#pragma unroll
    for (int k = lane; k < FDIM / 2; k += 32) s += hr[k] * w2[k];
#pragma unroll
    for (int o = 16; o; o >>= 1) s += __shfl_down_sync(0xffffffffu, s, o);
    if (lane == 0) out[g] = s + b2[0];
}

// ---------------- host launch ----------------
static inline void launch_gemm(const uint4* A16, const float* Afp, const uint4* B16,
                               const float* bias, float* C, uint4* O16, int M, int Mpad,
                               int Qa, int Nc, int act, float* stat, int Qout) {
    dim3 grid(Nc / 128, Mpad / 128);
    gemm_f16<<<grid, 256, GEMM_SMEM_BYTES>>>(A16, Afp, B16, bias, C, O16, M, Qa, Nc, act,
                                             stat, Qout);
}

extern "C" void kernel_launch(void* const* d_in, const int* in_sizes, int n_in,
                              void* d_out, int out_size) {
    const int* atomics = (const int*)d_in[0];
    const float* pos = (const float*)d_in[1];
    const int* edge_index = (const int*)d_in[2];
    const int* edge_attr = (const int*)d_in[3];
    const int* batch = (const int*)d_in[4];
    const float* x_emb1 = (const float*)d_in[5];
    const float* x_emb2_w = (const float*)d_in[6];
    const float* x_emb2_b = (const float*)d_in[7];
    const float* edge_emb = (const float*)d_in[8];
    const float* mlp_w1 = (const float*)d_in[9];
    const float* mlp_b1 = (const float*)d_in[10];
    const float* mlp_w2 = (const float*)d_in[11];
    const float* mlp_b2 = (const float*)d_in[12];
    const float* bn_gamma = (const float*)d_in[13];
    const float* bn_beta = (const float*)d_in[14];
    const float* feat_w = (const float*)d_in[15];
    const float* feat_b = (const float*)d_in[16];
    const float* head_w1 = (const float*)d_in[17];
    const float* head_b1 = (const float*)d_in[18];
    const float* head_w2 = (const float*)d_in[19];
    const float* head_b2 = (const float*)d_in[20];
    float* out = (float*)d_out;

    float *h, *agg, *stat, *ab, *ssum, *cnt, *pm, *gfeat, *hid;
    uint4 *a16b, *w16;
    int *deg, *fill, *rs, *bsum, *srcs, *attrs;
    cudaGetSymbolAddress((void**)&h, g_h);
    cudaGetSymbolAddress((void**)&agg, g_agg);
    cudaGetSymbolAddress((void**)&stat, g_stat);
    cudaGetSymbolAddress((void**)&ab, g_ab);
    cudaGetSymbolAddress((void**)&ssum, g_ssum);
    cudaGetSymbolAddress((void**)&cnt, g_cnt);
    cudaGetSymbolAddress((void**)&pm, g_pm);
    cudaGetSymbolAddress((void**)&gfeat, g_gfeat);
    cudaGetSymbolAddress((void**)&hid, g_hid);
    cudaGetSymbolAddress((void**)&a16b, g_a16b);
    cudaGetSymbolAddress((void**)&w16, g_w16);
    cudaGetSymbolAddress((void**)&deg, g_deg);
    cudaGetSymbolAddress((void**)&fill, g_fill);
    cudaGetSymbolAddress((void**)&rs, g_rs);
    cudaGetSymbolAddress((void**)&bsum, g_bsum);
    cudaGetSymbolAddress((void**)&srcs, g_srcs);
    cudaGetSymbolAddress((void**)&attrs, g_attrs);

    cudaFuncSetAttribute(gemm_f16, cudaFuncAttributeMaxDynamicSharedMemorySize,
                         GEMM_SMEM_BYTES);

    const size_t ND = (size_t)NN * DD;
    const size_t ND4 = ND / 4;
    const int EL = 256;

    // ---- CSR build ----
    csr_zero<<<(NN + EL - 1) / EL, EL>>>(deg, fill);
    csr_count<<<(EE + EL - 1) / EL, EL>>>(edge_index, deg);
    csr_scan1<<<NB_SCAN, 256>>>(deg, rs, bsum);
    csr_scan2<<<1, 512>>>(bsum);
    csr_scan3<<<NB_SCAN, 256>>>(rs, bsum);
    csr_place<<<(EE + EL - 1) / EL, EL>>>(edge_index, edge_attr, rs, fill, srcs, attrs);

    // ---- B16 prep (batched: 4 launches) ----
    conv_b16<<<640, 256>>>(mlp_w1, w16, DD, 2 * DD, LL);
    conv_b16<<<640, 256>>>(mlp_w2, w16 + 163840, 2 * DD, DD, LL);
    conv_b16<<<128, 256>>>(feat_w, w16 + 327680, DD, FDIM, 1);
    conv_b16<<<128, 256>>>(head_w1, w16 + 360448, FDIM, FDIM / 2, 1);

    init_h_kernel<<<(unsigned)((ND + EL - 1) / EL), EL>>>(atomics, pos, x_emb1, x_emb2_w,
                                                          x_emb2_b, h);
    zero_kernel<<<1, 512>>>(stat, 2 * DD);   // once; bn_finalize re-zeroes per layer

    for (int l = 0; l < LL; l++) {
        const float* emb_l = edge_emb + (size_t)l * NUM_BOND_C * DD;

        gather_edges_kernel<<<(NN + 7) / 8, 256>>>(h, srcs, attrs, rs, emb_l, agg);

        launch_gemm(nullptr, agg, w16 + l * 32768, mlp_b1 + (size_t)l * 2 * DD, nullptr,
                    a16b, NN, MPAD_N, DD / 16, 2 * DD, 1, nullptr, FDIM / 16);

        launch_gemm(a16b, nullptr, w16 + 163840 + l * 32768, mlp_b2 + (size_t)l * DD, h,
                    nullptr, NN, MPAD_N, FDIM / 16, DD, 0, stat, 1);

        bn_finalize_kernel<<<1, 256>>>(stat, bn_gamma + (size_t)l * DD,
                                       bn_beta + (size_t)l * DD, ab);

        if (l < LL - 1) {
            bn_apply_kernel<<<(unsigned)((ND4 + EL - 1) / EL), EL>>>(h, ab, 1);
        }
        // l == LL-1: BN affine commutes with mean pooling; applied in pm_kernel.
    }

    // ---- pool raw h, apply BN affine to pooled means ----
    pool_count_kernel<<<(NN + EL - 1) / EL, EL>>>(batch, cnt);
    {
        size_t total = ((NN + 7) / 8) * (size_t)(DD / 4);
        pool_sum_h_kernel<<<(unsigned)((total + EL - 1) / EL), EL>>>(h, batch, ssum);
    }
    pm_kernel<<<GG, 256>>>(ssum, cnt, ab, pm);

    // gfeat = pm @ feat_w + feat_b
    launch_gemm(nullptr, pm, w16 + 327680, feat_b, gfeat, nullptr, GG, MPAD_G, DD / 16,
                FDIM, 0, nullptr, 1);

    // head
    launch_gemm(nullptr, gfeat, w16 + 360448, head_b1, hid, nullptr, GG, MPAD_G, FDIM / 16,
                FDIM / 2, 1, nullptr, 1);
    head_out_kernel<<<(GG + 7) / 8, 256>>>(hid, head_w2, head_b2, out);
}